// round 7
// baseline (speedup 1.0000x reference)
#include <cuda_runtime.h>
#include <cuda_bf16.h>

// CBOW hierarchical-softmax loss.
// Inputs (metadata order):
//   d_in[0] context_idxs  int32 [B, C]   B=65536, C=10
//   d_in[1] path_nodes    int32 [B, D]   D=18
//   d_in[2] codes         int32 [B, D]
//   d_in[3] in_embed      f32   [V, E]   V=100000, E=128
//   d_in[4] node_embed    f32   [N, E]   N=99999
// Output: loss f32 [B]
//
// R7: pipe-split gathers. L1tex replays within-LDG wavefronts at ~2.07cyc,
//     so a 512B LDG.128 row costs ~8.3cyc of L1; a 4B/lane LDG.32 row-quarter
//     is 1 line = 1 wavefront at 1.0cyc but costs 4 LDG issue slots.
//     Split: 10 ctx rows via LDG.128 (wavefront pipe), 18 node rows via
//     4xLDG.32 (LSU issue pipe) -> both pipes ~40us, overlapped.
//     One 16-shfl transpose converts mean v from .128 to .32 ownership.
//     R4 packed butterfly + distributed epilogue kept.

#define B_ 65536
#define C_ 10
#define D_ 18
#define E_ 128
#define EPS_ 1e-9f

typedef unsigned long long u64;

__device__ __forceinline__ u64 f32x2_add(u64 a, u64 b) {
    u64 r; asm("add.rn.f32x2 %0, %1, %2;" : "=l"(r) : "l"(a), "l"(b)); return r;
}
__device__ __forceinline__ u64 f32x2_mul(u64 a, u64 b) {
    u64 r; asm("mul.rn.f32x2 %0, %1, %2;" : "=l"(r) : "l"(a), "l"(b)); return r;
}
__device__ __forceinline__ u64 pack2(float lo, float hi) {
    u64 r; asm("mov.b64 %0, {%1, %2};" : "=l"(r) : "f"(lo), "f"(hi)); return r;
}
__device__ __forceinline__ float2 unpack2(u64 v) {
    float2 f; asm("mov.b64 {%0, %1}, %2;" : "=f"(f.x), "=f"(f.y) : "l"(v)); return f;
}
__device__ __forceinline__ u64 shfl_xor_u64(u64 v, int o) {
    uint2 t; asm("mov.b64 {%0, %1}, %2;" : "=r"(t.x), "=r"(t.y) : "l"(v));
    t.x = __shfl_xor_sync(0xFFFFFFFFu, t.x, o);
    t.y = __shfl_xor_sync(0xFFFFFFFFu, t.y, o);
    u64 r; asm("mov.b64 %0, {%1, %2};" : "=l"(r) : "r"(t.x), "r"(t.y));
    return r;
}

__global__ void __launch_bounds__(256) cbow_hs_kernel(
    const int* __restrict__ ctx,
    const int* __restrict__ path,
    const int* __restrict__ codes,
    const float* __restrict__ in_emb,
    const float* __restrict__ node_emb,
    float* __restrict__ out)
{
    const int warp = (blockIdx.x * blockDim.x + threadIdx.x) >> 5;
    const int lane = threadIdx.x & 31;
    if (warp >= B_) return;

    const ulonglong2* __restrict__ in2 = reinterpret_cast<const ulonglong2*>(in_emb);

    // ---- indices: uniform int2 loads (1 wavefront each) ----
    const int2* __restrict__ ctx2 = reinterpret_cast<const int2*>(ctx + warp * C_);
    const int2* __restrict__ pn2  = reinterpret_cast<const int2*>(path + warp * D_);
    int cidx[C_], pn[D_];
#pragma unroll
    for (int j = 0; j < C_ / 2; j++) {
        int2 c = __ldg(&ctx2[j]);
        cidx[2 * j] = c.x; cidx[2 * j + 1] = c.y;
    }
#pragma unroll
    for (int j = 0; j < D_ / 2; j++) {
        int2 p = __ldg(&pn2[j]);
        pn[2 * j] = p.x; pn[2 * j + 1] = p.y;
    }
    int code_l = 0;
    if (lane < D_) code_l = __ldg(&codes[warp * D_ + lane]);

    // ---- context mean via LDG.128 (lane owns cols 4l..4l+3), packed adds ----
    u64 v01 = 0ull, v23 = 0ull;
#pragma unroll
    for (int j = 0; j < C_; j++) {
        ulonglong2 e = __ldg(&in2[(size_t)cidx[j] * (E_ / 4) + lane]);
        v01 = f32x2_add(v01, e.x);
        v23 = f32x2_add(v23, e.y);
    }
    const u64 inv = pack2(1.0f / (float)C_, 1.0f / (float)C_);
    v01 = f32x2_mul(v01, inv);
    v23 = f32x2_mul(v23, inv);

    // ---- transpose v from .128 ownership (cols 4l..4l+3) to .32
    //      ownership (cols {l, 32+l, 64+l, 96+l}) with 16 shfls ----
    float2 a01 = unpack2(v01), a23 = unpack2(v23);
    const float f0 = a01.x, f1 = a01.y, f2 = a23.x, f3 = a23.y;
    const int comp = lane & 3;
    const int base = lane >> 2;
    float w[4];
#pragma unroll
    for (int q = 0; q < 4; q++) {
        const int src = 8 * q + base;   // lane holding col 32q+l
        float t0 = __shfl_sync(0xFFFFFFFFu, f0, src);
        float t1 = __shfl_sync(0xFFFFFFFFu, f1, src);
        float t2 = __shfl_sync(0xFFFFFFFFu, f2, src);
        float t3 = __shfl_sync(0xFFFFFFFFu, f3, src);
        float r = (comp == 0) ? t0 : (comp == 1) ? t1 : (comp == 2) ? t2 : t3;
        w[q] = r;
    }

    // ---- node dots via 4x LDG.32 per row (each load = 1 cache line) ----
    float part[D_];
#pragma unroll
    for (int d = 0; d < D_; d++) {
        const float* __restrict__ r = node_emb + (size_t)pn[d] * E_ + lane;
        float n0 = __ldg(r);
        float n1 = __ldg(r + 32);
        float n2 = __ldg(r + 64);
        float n3 = __ldg(r + 96);
        part[d] = fmaf(n0, w[0], fmaf(n1, w[1], fmaf(n2, w[2], n3 * w[3])));
    }

    // ---- pair-packed butterfly: 9 u64 reduced across lanes in 5 steps ----
    u64 pair[D_ / 2];
#pragma unroll
    for (int j = 0; j < D_ / 2; j++)
        pair[j] = pack2(part[2 * j], part[2 * j + 1]);
#pragma unroll
    for (int o = 16; o > 0; o >>= 1) {
#pragma unroll
        for (int j = 0; j < D_ / 2; j++)
            pair[j] = f32x2_add(pair[j], shfl_xor_u64(pair[j], o));
    }

    // ---- lane d takes logit s_d ----
    const int mypair_idx = lane >> 1;
    u64 mypair = pair[0];
#pragma unroll
    for (int j = 1; j < D_ / 2; j++)
        mypair = (j == mypair_idx) ? pair[j] : mypair;
    float2 sp = unpack2(mypair);
    float s = (lane & 1) ? sp.y : sp.x;

    // ---- epilogue once per warp (3 MUFU total) ----
    float x = code_l ? s : -s;   // p = sigmoid(x) if code==1 else sigmoid(-x)
    float sig = __fdividef(1.0f, 1.0f + __expf(-x));
    float term = __logf(sig + EPS_);
    term = (lane < D_) ? term : 0.f;

#pragma unroll
    for (int o = 16; o > 0; o >>= 1)
        term += __shfl_xor_sync(0xFFFFFFFFu, term, o);

    if (lane == 0)
        out[warp] = -term;
}

extern "C" void kernel_launch(void* const* d_in, const int* in_sizes, int n_in,
                              void* d_out, int out_size)
{
    const int*   ctx      = (const int*)d_in[0];
    const int*   path     = (const int*)d_in[1];
    const int*   codes    = (const int*)d_in[2];
    const float* in_emb   = (const float*)d_in[3];
    const float* node_emb = (const float*)d_in[4];
    float*       out      = (float*)d_out;

    const int threads = 256;               // 8 warps/block
    const int total   = B_ * 32;
    const int blocks  = (total + threads - 1) / threads;
    cbow_hs_kernel<<<blocks, threads>>>(ctx, path, codes, in_emb, node_emb, out);
}

// round 8
// speedup vs baseline: 1.0988x; 1.0988x over previous
#include <cuda_runtime.h>
#include <cuda_bf16.h>

// CBOW hierarchical-softmax loss.
// Inputs (metadata order):
//   d_in[0] context_idxs  int32 [B, C]   B=65536, C=10
//   d_in[1] path_nodes    int32 [B, D]   D=18
//   d_in[2] codes         int32 [B, D]   d_in[3] in_embed f32 [V,E]
//   d_in[4] node_embed    f32   [N, E]   V=100000, N=99999, E=128
// Output: loss f32 [B]
//
// R8: pipe-split gathers WITH explicit MLP management.
//     ctx rows: LDG.128 (L1-wavefront pipe, 2 waves of 5, double-buffered)
//     node rows: 4x LDG.32 each (LSU-issue pipe, 1 line/load, 3 waves of 6
//     rows double-buffered). launch_bounds(256,3) ~85 regs so waves stay
//     register-resident (~50 loads in flight at peak). Mean + transpose
//     computed under node-wave latency. R7 transpose + R4 reduction/epilogue.

#define B_ 65536
#define C_ 10
#define D_ 18
#define E_ 128
#define EPS_ 1e-9f

typedef unsigned long long u64;

__device__ __forceinline__ u64 f32x2_add(u64 a, u64 b) {
    u64 r; asm("add.rn.f32x2 %0, %1, %2;" : "=l"(r) : "l"(a), "l"(b)); return r;
}
__device__ __forceinline__ u64 f32x2_mul(u64 a, u64 b) {
    u64 r; asm("mul.rn.f32x2 %0, %1, %2;" : "=l"(r) : "l"(a), "l"(b)); return r;
}
__device__ __forceinline__ u64 pack2(float lo, float hi) {
    u64 r; asm("mov.b64 %0, {%1, %2};" : "=l"(r) : "f"(lo), "f"(hi)); return r;
}
__device__ __forceinline__ float2 unpack2(u64 v) {
    float2 f; asm("mov.b64 {%0, %1}, %2;" : "=f"(f.x), "=f"(f.y) : "l"(v)); return f;
}
__device__ __forceinline__ u64 shfl_xor_u64(u64 v, int o) {
    uint2 t; asm("mov.b64 {%0, %1}, %2;" : "=r"(t.x), "=r"(t.y) : "l"(v));
    t.x = __shfl_xor_sync(0xFFFFFFFFu, t.x, o);
    t.y = __shfl_xor_sync(0xFFFFFFFFu, t.y, o);
    u64 r; asm("mov.b64 %0, {%1, %2};" : "=l"(r) : "r"(t.x), "r"(t.y));
    return r;
}

__global__ void __launch_bounds__(256, 3) cbow_hs_kernel(
    const int* __restrict__ ctx,
    const int* __restrict__ path,
    const int* __restrict__ codes,
    const float* __restrict__ in_emb,
    const float* __restrict__ node_emb,
    float* __restrict__ out)
{
    const int warp = (blockIdx.x * blockDim.x + threadIdx.x) >> 5;
    const int lane = threadIdx.x & 31;
    if (warp >= B_) return;

    const ulonglong2* __restrict__ in2 = reinterpret_cast<const ulonglong2*>(in_emb);

    // ---- indices first (short dependent chain for all gathers) ----
    const int2* __restrict__ ctx2 = reinterpret_cast<const int2*>(ctx + warp * C_);
    const int2* __restrict__ pn2  = reinterpret_cast<const int2*>(path + warp * D_);
    int cidx[C_], pn[D_];
#pragma unroll
    for (int j = 0; j < C_ / 2; j++) {
        int2 c = __ldg(&ctx2[j]);
        cidx[2 * j] = c.x; cidx[2 * j + 1] = c.y;
    }
#pragma unroll
    for (int j = 0; j < D_ / 2; j++) {
        int2 p = __ldg(&pn2[j]);
        pn[2 * j] = p.x; pn[2 * j + 1] = p.y;
    }
    int code_l = 0;
    if (lane < D_) code_l = __ldg(&codes[warp * D_ + lane]);

    // ---- ctx wave A (rows 0..4, LDG.128) in flight ----
    ulonglong2 ceA[5];
#pragma unroll
    for (int j = 0; j < 5; j++)
        ceA[j] = __ldg(&in2[(size_t)cidx[j] * (E_ / 4) + lane]);

    // ---- node wave 0 (rows 0..5, 4x LDG.32 each) in flight ----
    float a0[6][4];
#pragma unroll
    for (int d = 0; d < 6; d++) {
        const float* __restrict__ r = node_emb + (size_t)pn[d] * E_ + lane;
        a0[d][0] = __ldg(r);      a0[d][1] = __ldg(r + 32);
        a0[d][2] = __ldg(r + 64); a0[d][3] = __ldg(r + 96);
    }

    // ---- ctx wave B (rows 5..9) in flight ----
    ulonglong2 ceB[5];
#pragma unroll
    for (int j = 0; j < 5; j++)
        ceB[j] = __ldg(&in2[(size_t)cidx[5 + j] * (E_ / 4) + lane]);

    // ---- consume ctx wave A (packed adds) ----
    u64 v01 = 0ull, v23 = 0ull;
#pragma unroll
    for (int j = 0; j < 5; j++) {
        v01 = f32x2_add(v01, ceA[j].x);
        v23 = f32x2_add(v23, ceA[j].y);
    }

    // ---- node wave 1 (rows 6..11) in flight ----
    float a1[6][4];
#pragma unroll
    for (int d = 0; d < 6; d++) {
        const float* __restrict__ r = node_emb + (size_t)pn[6 + d] * E_ + lane;
        a1[d][0] = __ldg(r);      a1[d][1] = __ldg(r + 32);
        a1[d][2] = __ldg(r + 64); a1[d][3] = __ldg(r + 96);
    }

    // ---- consume ctx wave B, finish mean ----
#pragma unroll
    for (int j = 0; j < 5; j++) {
        v01 = f32x2_add(v01, ceB[j].x);
        v23 = f32x2_add(v23, ceB[j].y);
    }
    const u64 inv = pack2(1.0f / (float)C_, 1.0f / (float)C_);
    v01 = f32x2_mul(v01, inv);
    v23 = f32x2_mul(v23, inv);

    // ---- transpose v: .128 ownership (cols 4l..4l+3) -> .32 ownership
    //      (cols {l, 32+l, 64+l, 96+l}) with 16 shfls ----
    float2 a01 = unpack2(v01), a23 = unpack2(v23);
    const float g0 = a01.x, g1 = a01.y, g2 = a23.x, g3 = a23.y;
    const int comp = lane & 3;
    const int base = lane >> 2;
    float w[4];
#pragma unroll
    for (int q = 0; q < 4; q++) {
        const int src = 8 * q + base;   // lane holding col 32q+l
        float t0 = __shfl_sync(0xFFFFFFFFu, g0, src);
        float t1 = __shfl_sync(0xFFFFFFFFu, g1, src);
        float t2 = __shfl_sync(0xFFFFFFFFu, g2, src);
        float t3 = __shfl_sync(0xFFFFFFFFu, g3, src);
        w[q] = (comp == 0) ? t0 : (comp == 1) ? t1 : (comp == 2) ? t2 : t3;
    }

    // ---- node wave 2 (rows 12..17) in flight ----
    float a2[6][4];
#pragma unroll
    for (int d = 0; d < 6; d++) {
        const float* __restrict__ r = node_emb + (size_t)pn[12 + d] * E_ + lane;
        a2[d][0] = __ldg(r);      a2[d][1] = __ldg(r + 32);
        a2[d][2] = __ldg(r + 64); a2[d][3] = __ldg(r + 96);
    }

    // ---- consume node waves: two independent FMA chains per row ----
    float part[D_];
#pragma unroll
    for (int d = 0; d < 6; d++)
        part[d] = fmaf(a0[d][0], w[0], a0[d][2] * w[2]) +
                  fmaf(a0[d][1], w[1], a0[d][3] * w[3]);
#pragma unroll
    for (int d = 0; d < 6; d++)
        part[6 + d] = fmaf(a1[d][0], w[0], a1[d][2] * w[2]) +
                      fmaf(a1[d][1], w[1], a1[d][3] * w[3]);
#pragma unroll
    for (int d = 0; d < 6; d++)
        part[12 + d] = fmaf(a2[d][0], w[0], a2[d][2] * w[2]) +
                       fmaf(a2[d][1], w[1], a2[d][3] * w[3]);

    // ---- pair-packed butterfly: 9 u64 reduced across lanes in 5 steps ----
    u64 pair[D_ / 2];
#pragma unroll
    for (int j = 0; j < D_ / 2; j++)
        pair[j] = pack2(part[2 * j], part[2 * j + 1]);
#pragma unroll
    for (int o = 16; o > 0; o >>= 1) {
#pragma unroll
        for (int j = 0; j < D_ / 2; j++)
            pair[j] = f32x2_add(pair[j], shfl_xor_u64(pair[j], o));
    }

    // ---- lane d takes logit s_d ----
    const int mypair_idx = lane >> 1;
    u64 mypair = pair[0];
#pragma unroll
    for (int j = 1; j < D_ / 2; j++)
        mypair = (j == mypair_idx) ? pair[j] : mypair;
    float2 sp = unpack2(mypair);
    float s = (lane & 1) ? sp.y : sp.x;

    // ---- epilogue once per warp (3 MUFU total) ----
    float x = code_l ? s : -s;   // p = sigmoid(x) if code==1 else sigmoid(-x)
    float sig = __fdividef(1.0f, 1.0f + __expf(-x));
    float term = __logf(sig + EPS_);
    term = (lane < D_) ? term : 0.f;

#pragma unroll
    for (int o = 16; o > 0; o >>= 1)
        term += __shfl_xor_sync(0xFFFFFFFFu, term, o);

    if (lane == 0)
        out[warp] = -term;
}

extern "C" void kernel_launch(void* const* d_in, const int* in_sizes, int n_in,
                              void* d_out, int out_size)
{
    const int*   ctx      = (const int*)d_in[0];
    const int*   path     = (const int*)d_in[1];
    const int*   codes    = (const int*)d_in[2];
    const float* in_emb   = (const float*)d_in[3];
    const float* node_emb = (const float*)d_in[4];
    float*       out      = (float*)d_out;

    const int threads = 256;               // 8 warps/block
    const int total   = B_ * 32;
    const int blocks  = (total + threads - 1) / threads;
    cbow_hs_kernel<<<blocks, threads>>>(ctx, path, codes, in_emb, node_emb, out);
}

// round 9
// speedup vs baseline: 1.2634x; 1.1497x over previous
#include <cuda_runtime.h>
#include <cuda_bf16.h>

// CBOW hierarchical-softmax loss.
// Inputs (metadata order):
//   d_in[0] context_idxs  int32 [B, C]   B=65536, C=10
//   d_in[1] path_nodes    int32 [B, D]   D=18
//   d_in[2] codes         int32 [B, D]
//   d_in[3] in_embed      f32   [V, E]   V=100000, E=128
//   d_in[4] node_embed    f32   [N, E]   N=99999
// Output: loss f32 [B]
//
// R9 = R4 (best: flat 18x LDG.128, regs~40, occ 68%) + L2 evict_last cache
//      POLICY (createpolicy + ld.global.nc.L2::cache_hint, legal at any load
//      width unlike the static qualifier) on the 28 embedding-row gathers.
//      Tables total 102MB vs 126MB L2 -> keep them resident across graph
//      replays; index/code streams stay normal priority.

#define B_ 65536
#define C_ 10
#define D_ 18
#define E_ 128
#define EPS_ 1e-9f

typedef unsigned long long u64;

__device__ __forceinline__ u64 f32x2_add(u64 a, u64 b) {
    u64 r; asm("add.rn.f32x2 %0, %1, %2;" : "=l"(r) : "l"(a), "l"(b)); return r;
}
__device__ __forceinline__ u64 f32x2_mul(u64 a, u64 b) {
    u64 r; asm("mul.rn.f32x2 %0, %1, %2;" : "=l"(r) : "l"(a), "l"(b)); return r;
}
__device__ __forceinline__ u64 f32x2_fma(u64 a, u64 b, u64 c) {
    u64 r; asm("fma.rn.f32x2 %0, %1, %2, %3;" : "=l"(r) : "l"(a), "l"(b), "l"(c)); return r;
}
__device__ __forceinline__ u64 pack2(float lo, float hi) {
    u64 r; asm("mov.b64 %0, {%1, %2};" : "=l"(r) : "f"(lo), "f"(hi)); return r;
}
__device__ __forceinline__ float2 unpack2(u64 v) {
    float2 f; asm("mov.b64 {%0, %1}, %2;" : "=f"(f.x), "=f"(f.y) : "l"(v)); return f;
}
__device__ __forceinline__ u64 shfl_xor_u64(u64 v, int o) {
    uint2 t; asm("mov.b64 {%0, %1}, %2;" : "=r"(t.x), "=r"(t.y) : "l"(v));
    t.x = __shfl_xor_sync(0xFFFFFFFFu, t.x, o);
    t.y = __shfl_xor_sync(0xFFFFFFFFu, t.y, o);
    u64 r; asm("mov.b64 %0, {%1, %2};" : "=l"(r) : "r"(t.x), "r"(t.y));
    return r;
}
// L2 evict_last access policy (keep embedding tables resident).
__device__ __forceinline__ u64 mk_policy_evict_last() {
    u64 p; asm("createpolicy.fractional.L2::evict_last.b64 %0, 1.0;" : "=l"(p));
    return p;
}
// 16B row gather with L2 cache-policy hint.
__device__ __forceinline__ ulonglong2 ldrow(const ulonglong2* a, u64 pol) {
    ulonglong2 v;
    asm("ld.global.nc.L2::cache_hint.v2.u64 {%0, %1}, [%2], %3;"
        : "=l"(v.x), "=l"(v.y) : "l"(a), "l"(pol));
    return v;
}

__global__ void __launch_bounds__(256) cbow_hs_kernel(
    const int* __restrict__ ctx,
    const int* __restrict__ path,
    const int* __restrict__ codes,
    const float* __restrict__ in_emb,
    const float* __restrict__ node_emb,
    float* __restrict__ out)
{
    const int warp = (blockIdx.x * blockDim.x + threadIdx.x) >> 5;
    const int lane = threadIdx.x & 31;
    if (warp >= B_) return;

    const u64 pol = mk_policy_evict_last();

    // Rows viewed as ulonglong2: 128 f32 = 32 x 16B per row; lane owns one.
    const ulonglong2* __restrict__ in2 = reinterpret_cast<const ulonglong2*>(in_emb);
    const ulonglong2* __restrict__ nd2 = reinterpret_cast<const ulonglong2*>(node_emb);

    // ---- per-lane code: one coalesced 72B LDG per warp ----
    int code_l = 0;
    if (lane < D_) code_l = __ldg(&codes[warp * D_ + lane]);

    // ---- context indices: 5 x int2 (rows 40B, 8B-aligned) ----
    const int2* __restrict__ ctx2 = reinterpret_cast<const int2*>(ctx + warp * C_);
    int cidx[C_];
#pragma unroll
    for (int j = 0; j < C_ / 2; j++) {
        int2 c = __ldg(&ctx2[j]);
        cidx[2 * j]     = c.x;
        cidx[2 * j + 1] = c.y;
    }

    // ---- context mean: v (10 independent 512B row gathers, packed adds) ----
    u64 v01 = 0ull, v23 = 0ull;
#pragma unroll
    for (int j = 0; j < C_; j++) {
        ulonglong2 e = ldrow(&in2[(size_t)cidx[j] * (E_ / 4) + lane], pol);
        v01 = f32x2_add(v01, e.x);
        v23 = f32x2_add(v23, e.y);
    }
    const u64 inv = pack2(1.0f / (float)C_, 1.0f / (float)C_);
    v01 = f32x2_mul(v01, inv);
    v23 = f32x2_mul(v23, inv);

    // ---- path indices: 9 x int2 (rows 72B, 8B-aligned) ----
    const int2* __restrict__ pn2 = reinterpret_cast<const int2*>(path + warp * D_);
    int pn[D_];
#pragma unroll
    for (int j = 0; j < D_ / 2; j++) {
        int2 p = __ldg(&pn2[j]);
        pn[2 * j] = p.x; pn[2 * j + 1] = p.y;
    }

    // ---- 18 independent node-row gathers -> 9 packed per-lane partials ----
    u64 pair[D_ / 2];
#pragma unroll
    for (int j = 0; j < D_ / 2; j++) {
        ulonglong2 u0 = ldrow(&nd2[(size_t)pn[2 * j]     * (E_ / 4) + lane], pol);
        ulonglong2 u1 = ldrow(&nd2[(size_t)pn[2 * j + 1] * (E_ / 4) + lane], pol);
        u64 m0 = f32x2_fma(u0.y, v23, f32x2_mul(u0.x, v01));
        u64 m1 = f32x2_fma(u1.y, v23, f32x2_mul(u1.x, v01));
        float2 f0 = unpack2(m0);
        float2 f1 = unpack2(m1);
        pair[j] = pack2(f0.x + f0.y, f1.x + f1.y);
    }

    // ---- pair-packed butterfly: 9 u64 reduced across lanes in 5 steps ----
#pragma unroll
    for (int o = 16; o > 0; o >>= 1) {
#pragma unroll
        for (int j = 0; j < D_ / 2; j++)
            pair[j] = f32x2_add(pair[j], shfl_xor_u64(pair[j], o));
    }

    // ---- capture this lane's logit: lane d takes s_d ----
    const int mypair_idx = lane >> 1;
    u64 mypair = pair[0];
#pragma unroll
    for (int j = 1; j < D_ / 2; j++)
        mypair = (j == mypair_idx) ? pair[j] : mypair;
    float2 sp = unpack2(mypair);
    float s = (lane & 1) ? sp.y : sp.x;

    // ---- epilogue once per warp (3 MUFU instead of 54) ----
    float x = code_l ? s : -s;   // p = sigmoid(x) if code==1 else sigmoid(-x)
    float sig = __fdividef(1.0f, 1.0f + __expf(-x));
    float term = __logf(sig + EPS_);
    term = (lane < D_) ? term : 0.f;

    // ---- sum the 18 log terms across lanes ----
#pragma unroll
    for (int o = 16; o > 0; o >>= 1)
        term += __shfl_xor_sync(0xFFFFFFFFu, term, o);

    if (lane == 0)
        out[warp] = -term;
}

extern "C" void kernel_launch(void* const* d_in, const int* in_sizes, int n_in,
                              void* d_out, int out_size)
{
    const int*   ctx      = (const int*)d_in[0];
    const int*   path     = (const int*)d_in[1];
    const int*   codes    = (const int*)d_in[2];
    const float* in_emb   = (const float*)d_in[3];
    const float* node_emb = (const float*)d_in[4];
    float*       out      = (float*)d_out;

    const int threads = 256;               // 8 warps/block
    const int total   = B_ * 32;
    const int blocks  = (total + threads - 1) / threads;
    cbow_hs_kernel<<<blocks, threads>>>(ctx, path, codes, in_emb, node_emb, out);
}